// round 9
// baseline (speedup 1.0000x reference)
#include <cuda_runtime.h>
#include <math.h>

// ---------------------------------------------------------------------------
// NoisyTopkRouter: B=128, T1=128, T2=8, D=1024, E=64
// Two kernels:
//  1) pool_kernel: FINE-GRAINED mean-pool, grid (B,32) x 256 thr, 32 rows per
//     CTA -> 4096 CTAs = 4 waves on 148 SMs. Multi-wave work-stealing absorbs
//     the single-wave CTA-completion spread (L2-die variance + L1tex queue)
//     that capped the old 1-wave pool at ~86% DRAM-active.
//  2) router_kernel: proven R2 shape, 128 blocks x 1024 thr, 1 batch each;
//     sums 32 partials (L2-resident), dual GEMV, softmax chain.
// Outputs: router_output [B,E] then noisy [B,E].
// ---------------------------------------------------------------------------

#define B_ 128
#define TT 1024   // T1*T2
#define D_ 1024
#define E_ 64
#define TSPLIT 32
#define TCHUNK (TT / TSPLIT)  // 32

// partials: [B][TSPLIT][256] float4 = 16 MiB
__device__ float4 g_partial[B_ * TSPLIT * 256];

__global__ void __launch_bounds__(256) pool_kernel(const float* __restrict__ mh) {
    const int b   = blockIdx.x;
    const int ts  = blockIdx.y;
    const int tid = threadIdx.x;

    const float4* p = reinterpret_cast<const float4*>(
        mh + ((size_t)b * TT + (size_t)ts * TCHUNK) * D_) + tid;

    float4 acc = make_float4(0.f, 0.f, 0.f, 0.f);
#pragma unroll 8
    for (int t = 0; t < TCHUNK; ++t) {
        float4 v = __ldcs(p + (size_t)t * (D_ / 4));  // streaming: no reuse
        acc.x += v.x; acc.y += v.y; acc.z += v.z; acc.w += v.w;
    }
    g_partial[(b * TSPLIT + ts) * 256 + tid] = acc;
}

__device__ __forceinline__ float softplus_f(float x) {
    // jax.nn.softplus = logaddexp(x, 0)
    return fmaxf(x, 0.f) + log1pf(expf(-fabsf(x)));
}

// 128 blocks x 1024 threads; one batch per block (proven R2 shape).
// Warp w: experts w and w+32, both matrices.
__global__ void __launch_bounds__(1024) router_kernel(
    const float* __restrict__ W_route, const float* __restrict__ b_route,
    const float* __restrict__ W_noise, const float* __restrict__ b_noise,
    const float* __restrict__ noise_eps, const int* __restrict__ mis_mask,
    float* __restrict__ out, int out_size)
{
    __shared__ __align__(16) float pooled[D_];
    __shared__ float lraw[E_], nraw[E_];
    __shared__ float ebuf1[E_], ebuf2[E_];
    __shared__ float noisy_s[E_], sparse_s[E_];

    const int b   = blockIdx.x;
    const int tid = threadIdx.x;

    // --- finish pooling: thread owns d=tid, sums 32 partials (mostly L2 hits) ---
    {
        const float* gp = reinterpret_cast<const float*>(g_partial);
        float acc = 0.f;
#pragma unroll 8
        for (int t = 0; t < TSPLIT; ++t)
            acc += gp[((size_t)(b * TSPLIT + t)) * 1024 + tid];
        pooled[tid] = acc * (1.0f / (float)TT);
    }
    __syncthreads();

    // --- dual GEMV: warp w -> experts w and w+32; float4 lanes over D ---
    {
        const int w = tid >> 5, lane = tid & 31;
        const float4* pooled4 = reinterpret_cast<const float4*>(pooled);
#pragma unroll
        for (int ei = 0; ei < 2; ++ei) {
            const int e = w + ei * 32;
            const float4* wr = reinterpret_cast<const float4*>(W_route) + (size_t)e * (D_ / 4);
            const float4* wn = reinterpret_cast<const float4*>(W_noise) + (size_t)e * (D_ / 4);
            float ar = 0.f, an = 0.f;
#pragma unroll
            for (int j = lane; j < D_ / 4; j += 32) {
                float4 pv = pooled4[j];
                float4 a  = __ldg(wr + j);
                float4 c  = __ldg(wn + j);
                ar += pv.x * a.x + pv.y * a.y + pv.z * a.z + pv.w * a.w;
                an += pv.x * c.x + pv.y * c.y + pv.z * c.z + pv.w * c.w;
            }
#pragma unroll
            for (int o = 16; o; o >>= 1) {
                ar += __shfl_xor_sync(0xffffffffu, ar, o);
                an += __shfl_xor_sync(0xffffffffu, an, o);
            }
            if (lane == 0) {
                lraw[e] = ar + b_route[e];
                nraw[e] = an + b_noise[e];
            }
        }
    }
    __syncthreads();

    // --- per-expert scalar chain; tid<64 active, all threads hit syncthreads ---
    float logit = 0.f;

    if (tid < E_) {
        float m1 = -INFINITY;
#pragma unroll
        for (int j = 0; j < E_; ++j) m1 = fmaxf(m1, lraw[j]);
        ebuf1[tid] = expf(lraw[tid] - m1);
        nraw[tid] = noise_eps[b * E_ + tid] * softplus_f(nraw[tid]);
    }
    __syncthreads();

    if (tid < E_) {
        float s1 = 0.f;
#pragma unroll
        for (int j = 0; j < E_; ++j) s1 += ebuf1[j];
        logit = ebuf1[tid] / s1;

        float m2 = -INFINITY;
#pragma unroll
        for (int j = 0; j < E_; ++j) m2 = fmaxf(m2, nraw[j]);
        ebuf2[tid] = expf(nraw[tid] - m2);
    }
    __syncthreads();

    if (tid < E_) {
        float s2 = 0.f;
#pragma unroll
        for (int j = 0; j < E_; ++j) s2 += ebuf2[j];
        float noisy = logit + ebuf2[tid] / s2;
        noisy_s[tid] = noisy;
        if (out_size >= 2 * B_ * E_)
            out[B_ * E_ + b * E_ + tid] = noisy;   // second output: noisy
    }
    __syncthreads();

    if (tid < E_) {
        // stable descending rank (ties -> lower index first)
        const float myv = noisy_s[tid];
        int rank = 0;
#pragma unroll
        for (int j = 0; j < E_; ++j) {
            float vj = noisy_s[j];
            rank += (vj > myv) || (vj == myv && j < tid);
        }
        const int k = mis_mask[b];
        float sp = (rank < k) ? myv : 0.f;
        if (k < E_ && tid == 0) sp = 0.f;   // torch pad-scatter quirk
        sparse_s[tid] = sp;
    }
    __syncthreads();

    if (tid < E_) {
        float m3 = -INFINITY;
#pragma unroll
        for (int j = 0; j < E_; ++j) m3 = fmaxf(m3, sparse_s[j]);
        ebuf1[tid] = expf(sparse_s[tid] - m3);
    }
    __syncthreads();

    if (tid < E_) {
        float s3 = 0.f;
#pragma unroll
        for (int j = 0; j < E_; ++j) s3 += ebuf1[j];
        out[b * E_ + tid] = ebuf1[tid] / s3;       // first output: router_output
    }
}

extern "C" void kernel_launch(void* const* d_in, const int* in_sizes, int n_in,
                              void* d_out, int out_size) {
    const float* mh        = (const float*)d_in[0];
    const float* W_route   = (const float*)d_in[1];
    const float* b_route   = (const float*)d_in[2];
    const float* W_noise   = (const float*)d_in[3];
    const float* b_noise   = (const float*)d_in[4];
    const float* noise_eps = (const float*)d_in[5];
    const int*   mis_mask  = (const int*)d_in[6];
    float* out = (float*)d_out;

    dim3 g1(B_, TSPLIT);
    pool_kernel<<<g1, 256>>>(mh);
    router_kernel<<<B_, 1024>>>(W_route, b_route, W_noise, b_noise,
                                noise_eps, mis_mask, out, out_size);
}

// round 10
// speedup vs baseline: 1.0309x; 1.0309x over previous
#include <cuda_runtime.h>
#include <math.h>

// ---------------------------------------------------------------------------
// NoisyTopkRouter: B=128, T1=128, T2=8, D=1024, E=64
// Two kernels (proven R2 structure, 88.3us):
//  1) pool_kernel: mean-pool 512MB stream, grid (B,8) x 256 thr, unroll-8
//     float4 __ldcs  (~80us, ~6.8TB/s in-phase = near ceiling).
//  2) router_kernel: 128 blocks x 1024 thr, one batch each. NEW: opens with a
//     prefetch.global.L2 preamble (each block warms a distinct 4KB W slice;
//     128 blocks cover all 512KB) so the W fetch overlaps the partial-read
//     latency phase instead of serializing after it.
// Outputs: router_output [B,E] then noisy [B,E].
// ---------------------------------------------------------------------------

#define B_ 128
#define TT 1024   // T1*T2
#define D_ 1024
#define E_ 64
#define TSPLIT 8
#define TCHUNK (TT / TSPLIT)  // 128

// partials: [B][TSPLIT][256] float4 = 4 MiB
__device__ float4 g_partial[B_ * TSPLIT * 256];

__global__ void __launch_bounds__(256) pool_kernel(const float* __restrict__ mh) {
    const int b   = blockIdx.x;
    const int ts  = blockIdx.y;
    const int tid = threadIdx.x;

    const float4* p = reinterpret_cast<const float4*>(
        mh + ((size_t)b * TT + (size_t)ts * TCHUNK) * D_) + tid;

    float4 acc = make_float4(0.f, 0.f, 0.f, 0.f);
#pragma unroll 8
    for (int t = 0; t < TCHUNK; ++t) {
        float4 v = __ldcs(p + (size_t)t * (D_ / 4));  // streaming: no reuse
        acc.x += v.x; acc.y += v.y; acc.z += v.z; acc.w += v.w;
    }
    g_partial[(b * TSPLIT + ts) * 256 + tid] = acc;
}

__device__ __forceinline__ float softplus_f(float x) {
    // jax.nn.softplus = logaddexp(x, 0)
    return fmaxf(x, 0.f) + log1pf(expf(-fabsf(x)));
}

// 128 blocks x 1024 threads; one batch per block.
// Warp w: experts w and w+32, both matrices.
__global__ void __launch_bounds__(1024) router_kernel(
    const float* __restrict__ W_route, const float* __restrict__ b_route,
    const float* __restrict__ W_noise, const float* __restrict__ b_noise,
    const float* __restrict__ noise_eps, const int* __restrict__ mis_mask,
    float* __restrict__ out, int out_size)
{
    __shared__ __align__(16) float pooled[D_];
    __shared__ float lraw[E_], nraw[E_];
    __shared__ float ebuf1[E_], ebuf2[E_];
    __shared__ float noisy_s[E_], sparse_s[E_];

    const int b   = blockIdx.x;
    const int tid = threadIdx.x;

    // --- W L2-warm preamble: block b prefetches a distinct 4KB slice
    //     (2KB per matrix = 16 x 128B lines each); 128 blocks cover all 512KB.
    //     Overlaps the W DRAM fetch with the partial-read phase below. ---
    {
        const char* wr = reinterpret_cast<const char*>(W_route) + (size_t)b * 2048;
        const char* wn = reinterpret_cast<const char*>(W_noise) + (size_t)b * 2048;
        if (tid < 16)
            asm volatile("prefetch.global.L2 [%0];" :: "l"(wr + (size_t)tid * 128));
        else if (tid < 32)
            asm volatile("prefetch.global.L2 [%0];" :: "l"(wn + (size_t)(tid - 16) * 128));
    }

    // --- finish pooling: thread owns d=tid, sums 8 partials ---
    {
        const float* gp = reinterpret_cast<const float*>(g_partial);
        float acc = 0.f;
#pragma unroll
        for (int t = 0; t < TSPLIT; ++t)
            acc += gp[((size_t)(b * TSPLIT + t)) * 1024 + tid];
        pooled[tid] = acc * (1.0f / (float)TT);
    }
    __syncthreads();

    // --- dual GEMV: warp w -> experts w and w+32; float4 lanes over D ---
    {
        const int w = tid >> 5, lane = tid & 31;
        const float4* pooled4 = reinterpret_cast<const float4*>(pooled);
#pragma unroll
        for (int ei = 0; ei < 2; ++ei) {
            const int e = w + ei * 32;
            const float4* wr = reinterpret_cast<const float4*>(W_route) + (size_t)e * (D_ / 4);
            const float4* wn = reinterpret_cast<const float4*>(W_noise) + (size_t)e * (D_ / 4);
            float ar = 0.f, an = 0.f;
#pragma unroll
            for (int j = lane; j < D_ / 4; j += 32) {
                float4 pv = pooled4[j];
                float4 a  = __ldg(wr + j);
                float4 c  = __ldg(wn + j);
                ar += pv.x * a.x + pv.y * a.y + pv.z * a.z + pv.w * a.w;
                an += pv.x * c.x + pv.y * c.y + pv.z * c.z + pv.w * c.w;
            }
#pragma unroll
            for (int o = 16; o; o >>= 1) {
                ar += __shfl_xor_sync(0xffffffffu, ar, o);
                an += __shfl_xor_sync(0xffffffffu, an, o);
            }
            if (lane == 0) {
                lraw[e] = ar + b_route[e];
                nraw[e] = an + b_noise[e];
            }
        }
    }
    __syncthreads();

    // --- per-expert scalar chain; tid<64 active, all threads hit syncthreads ---
    float logit = 0.f;

    if (tid < E_) {
        float m1 = -INFINITY;
#pragma unroll
        for (int j = 0; j < E_; ++j) m1 = fmaxf(m1, lraw[j]);
        ebuf1[tid] = expf(lraw[tid] - m1);
        nraw[tid] = noise_eps[b * E_ + tid] * softplus_f(nraw[tid]);
    }
    __syncthreads();

    if (tid < E_) {
        float s1 = 0.f;
#pragma unroll
        for (int j = 0; j < E_; ++j) s1 += ebuf1[j];
        logit = ebuf1[tid] / s1;

        float m2 = -INFINITY;
#pragma unroll
        for (int j = 0; j < E_; ++j) m2 = fmaxf(m2, nraw[j]);
        ebuf2[tid] = expf(nraw[tid] - m2);
    }
    __syncthreads();

    if (tid < E_) {
        float s2 = 0.f;
#pragma unroll
        for (int j = 0; j < E_; ++j) s2 += ebuf2[j];
        float noisy = logit + ebuf2[tid] / s2;
        noisy_s[tid] = noisy;
        if (out_size >= 2 * B_ * E_)
            out[B_ * E_ + b * E_ + tid] = noisy;   // second output: noisy
    }
    __syncthreads();

    if (tid < E_) {
        // stable descending rank (ties -> lower index first)
        const float myv = noisy_s[tid];
        int rank = 0;
#pragma unroll
        for (int j = 0; j < E_; ++j) {
            float vj = noisy_s[j];
            rank += (vj > myv) || (vj == myv && j < tid);
        }
        const int k = mis_mask[b];
        float sp = (rank < k) ? myv : 0.f;
        if (k < E_ && tid == 0) sp = 0.f;   // torch pad-scatter quirk
        sparse_s[tid] = sp;
    }
    __syncthreads();

    if (tid < E_) {
        float m3 = -INFINITY;
#pragma unroll
        for (int j = 0; j < E_; ++j) m3 = fmaxf(m3, sparse_s[j]);
        ebuf1[tid] = expf(sparse_s[tid] - m3);
    }
    __syncthreads();

    if (tid < E_) {
        float s3 = 0.f;
#pragma unroll
        for (int j = 0; j < E_; ++j) s3 += ebuf1[j];
        out[b * E_ + tid] = ebuf1[tid] / s3;       // first output: router_output
    }
}

extern "C" void kernel_launch(void* const* d_in, const int* in_sizes, int n_in,
                              void* d_out, int out_size) {
    const float* mh        = (const float*)d_in[0];
    const float* W_route   = (const float*)d_in[1];
    const float* b_route   = (const float*)d_in[2];
    const float* W_noise   = (const float*)d_in[3];
    const float* b_noise   = (const float*)d_in[4];
    const float* noise_eps = (const float*)d_in[5];
    const int*   mis_mask  = (const int*)d_in[6];
    float* out = (float*)d_out;

    dim3 g1(B_, TSPLIT);
    pool_kernel<<<g1, 256>>>(mh);
    router_kernel<<<B_, 1024>>>(W_route, b_route, W_noise, b_noise,
                                noise_eps, mis_mask, out, out_size);
}